// round 12
// baseline (speedup 1.0000x reference)
#include <cuda_runtime.h>

#define NLVL   16
#define WIDTH  1000
#define PADW   (WIDTH + 4)     // w in [-2, 1001]
#define TPB    768             // 24 warps, 85-reg cap: room for pipelined live state

typedef unsigned long long u64;
typedef unsigned int       u32;

// ---------------- packed f32x2 helpers ----------------
__device__ __forceinline__ u64 pk(float lo, float hi) {
    u64 r; asm("mov.b64 %0, {%1,%2};" : "=l"(r) : "f"(lo), "f"(hi)); return r;
}
__device__ __forceinline__ void upk(float& lo, float& hi, u64 v) {
    asm("mov.b64 {%0,%1}, %2;" : "=f"(lo), "=f"(hi) : "l"(v));
}
__device__ __forceinline__ u64 f2fma(u64 a, u64 b, u64 c) {
    u64 r; asm("fma.rn.f32x2 %0, %1, %2, %3;" : "=l"(r) : "l"(a), "l"(b), "l"(c)); return r;
}
__device__ __forceinline__ u64 f2add(u64 a, u64 b) {
    u64 r; asm("add.rn.f32x2 %0, %1, %2;" : "=l"(r) : "l"(a), "l"(b)); return r;
}
__device__ __forceinline__ u64 f2sub(u64 a, u64 b) {
    u64 r; asm("sub.rn.f32x2 %0, %1, %2;" : "=l"(r) : "l"(a), "l"(b)); return r;
}
__device__ __forceinline__ u64 f2mul(u64 a, u64 b) {
    u64 r; asm("mul.rn.f32x2 %0, %1, %2;" : "=l"(r) : "l"(a), "l"(b)); return r;
}
__device__ __forceinline__ u64 bc(float v) { return pk(v, v); }

__device__ __forceinline__ float hwsin(float r) {   // r in [-pi, pi]
    float s; asm("sin.approx.f32 %0, %1;" : "=f"(s) : "f"(r)); return s;
}

__global__ __launch_bounds__(TPB, 1)
void trig_hash_kernel(const float* __restrict__ x,
                      const float* __restrict__ grids,
                      const float* __restrict__ G,
                      const float* __restrict__ H,
                      float2* __restrict__ out,
                      int n_pairs)     // (B/2)*16
{
    extern __shared__ float2 gsm[];    // [(w+2)*16 + n] : conflict-free (half-warp phases)

    // Stage grids (N,C,W) -> transposed padded smem. Zeros outside [0,W).
    for (int j = threadIdx.x; j < PADW * NLVL; j += TPB) {
        int n = j & (NLVL - 1);
        int w = (j >> 4) - 2;
        float c0 = 0.f, c1 = 0.f;
        if ((unsigned)w < (unsigned)WIDTH) {
            c0 = grids[(n * 2 + 0) * WIDTH + w];
            c1 = grids[(n * 2 + 1) * WIDTH + w];
        }
        gsm[j] = make_float2(c0, c1);
    }
    __syncthreads();

    const int gtid   = blockIdx.x * TPB + threadIdx.x;
    const int stride = gridDim.x * TPB;       // multiple of 16
    const int n      = gtid & (NLVL - 1);

    // Per-level constants pre-scaled to TURNS (fold 1/2pi into G, H).
    const float S = 0.15915494309189535f;
    const u64 G00 = bc(G[  0 + n]*S), G01 = bc(G[ 16 + n]*S), G02 = bc(G[ 32 + n]*S);
    const u64 G10 = bc(G[ 48 + n]*S), G11 = bc(G[ 64 + n]*S), G12 = bc(G[ 80 + n]*S);
    const u64 G20 = bc(G[ 96 + n]*S), G21 = bc(G[112 + n]*S), G22 = bc(G[128 + n]*S);
    const u64 H0  = bc(H[  0 + n]*S), H1  = bc(H[ 16 + n]*S), H2  = bc(H[ 32 + n]*S);

    const u64 MAGIC = bc(12582912.0f);               // 1.5 * 2^23
    const u64 TWOPI = bc(6.2831853071795865f);
    const u64 ONEp  = bc(1.0f);
    const u64 C075p = bc(0.75f);
    const u64 C125p = bc(1.25f);
    const float MAG499 = 12583411.0f;                // 12582912 + 499, exact

    u32 smbase;
    asm("{ .reg .u64 t; cvta.to.shared.u64 t, %1; cvt.u32.u64 %0, t; }"
        : "=r"(smbase) : "l"(gsm));
    // addr(tap0) = bits(bb)*128 + addrc   (0x4B400000*128 mod 2^32 = 0xA0000000)
    const u32 addrc = smbase + 128u + (u32)(n * 8) - 0xA0000000u;

    // ================= stage-1 (address generation) as a macro-like lambda ======
    auto stage1 = [&](float2 s0, float2 s1, float2 s2,
                      u64& tp_o, u32& adA_o, u32& adB_o) {
        u64 X0 = pk(s0.x, s1.y);
        u64 X1 = pk(s0.y, s2.x);
        u64 X2 = pk(s1.x, s2.y);
        u64 a0 = f2fma(X0, G00, f2fma(X1, G10, f2fma(X2, G20, H0)));
        u64 a1 = f2fma(X0, G01, f2fma(X1, G11, f2fma(X2, G21, H1)));
        u64 a2 = f2fma(X0, G02, f2fma(X1, G12, f2fma(X2, G22, H2)));
        // turns-domain reduction: rt = a - rint(a) (exact), then *2pi
        u64 kb0 = f2add(a0, MAGIC), kb1 = f2add(a1, MAGIC), kb2 = f2add(a2, MAGIC);
        u64 rr0 = f2mul(f2sub(a0, f2sub(kb0, MAGIC)), TWOPI);
        u64 rr1 = f2mul(f2sub(a1, f2sub(kb1, MAGIC)), TWOPI);
        u64 rr2 = f2mul(f2sub(a2, f2sub(kb2, MAGIC)), TWOPI);
        float r0A, r0B, r1A, r1B, r2A, r2B;
        upk(r0A, r0B, rr0); upk(r1A, r1B, rr1); upk(r2A, r2B, rr2);
        float gxA = hwsin(r0A) * hwsin(r1A) * hwsin(r2A);
        float gxB = hwsin(r0B) * hwsin(r1B) * hwsin(r2B);
        // fused ix chain: ix = 500*gx + 499.5
        float bbA = fmaf(gxA, 500.0f, MAG499);        // MAGIC + floor(ix)
        float bbB = fmaf(gxB, 500.0f, MAG499);
        float xfA = bbA - 12582912.0f;
        float xfB = bbB - 12582912.0f;
        float tA  = fmaf(gxA, 500.0f, 499.5f - xfA);  // t = ix - base
        float tB  = fmaf(gxB, 500.0f, 499.5f - xfB);
        tp_o  = pk(tA, tB);
        adA_o = __float_as_uint(bbA) * 128u + addrc;
        adB_o = __float_as_uint(bbB) * 128u + addrc;
    };

    // ================= prologue: stage-1 for p0, prefetch x for p0+stride ======
    u64 ctp; u32 cadA, cadB;
    {
        int g = ((gtid < n_pairs) ? gtid : 0) >> 4;
        const float2* xp = (const float2*)(x + 6 * g);
        stage1(xp[0], xp[1], xp[2], ctp, cadA, cadB);
    }
    float2 q0, q1, q2;
    {
        int pq = gtid + stride;
        int g  = ((pq < n_pairs) ? pq : ((gtid < n_pairs) ? gtid : 0)) >> 4;
        const float2* xp = (const float2*)(x + 6 * g);
        q0 = xp[0]; q1 = xp[1]; q2 = xp[2];
    }

    for (int p = gtid; p < n_pairs; p += stride) {
        // ---- issue all 8 tap loads for CURRENT p from carried addresses ----
        float a0x,a0y,a1x,a1y,a2x,a2y,a3x,a3y;
        float b0x,b0y,b1x,b1y,b2x,b2y,b3x,b3y;
        asm("ld.shared.v2.f32 {%0,%1},[%2];"     : "=f"(a0x), "=f"(a0y) : "r"(cadA));
        asm("ld.shared.v2.f32 {%0,%1},[%2+128];" : "=f"(a1x), "=f"(a1y) : "r"(cadA));
        asm("ld.shared.v2.f32 {%0,%1},[%2+256];" : "=f"(a2x), "=f"(a2y) : "r"(cadA));
        asm("ld.shared.v2.f32 {%0,%1},[%2+384];" : "=f"(a3x), "=f"(a3y) : "r"(cadA));
        asm("ld.shared.v2.f32 {%0,%1},[%2];"     : "=f"(b0x), "=f"(b0y) : "r"(cadB));
        asm("ld.shared.v2.f32 {%0,%1},[%2+128];" : "=f"(b1x), "=f"(b1y) : "r"(cadB));
        asm("ld.shared.v2.f32 {%0,%1},[%2+256];" : "=f"(b2x), "=f"(b2y) : "r"(cadB));
        asm("ld.shared.v2.f32 {%0,%1},[%2+384];" : "=f"(b3x), "=f"(b3y) : "r"(cadB));

        // ---- prefetch x two iterations ahead ----
        int pf = p + 2 * stride;
        int gf = ((pf < n_pairs) ? pf : p) >> 4;
        const float2* xf = (const float2*)(x + 6 * gf);
        float2 f0 = xf[0], f1 = xf[1], f2v = xf[2];

        // ---- stage-1 for p+stride (long independent stream: hides LDS+MUFU) ----
        u64 ntp; u32 nadA, nadB;
        stage1(q0, q1, q2, ntp, nadA, nadB);

        // ---- weights for CURRENT p from carried t (u = t^2 - t factorization) ----
        u64 tm1 = f2sub(ctp, ONEp);
        u64 u   = f2mul(ctp, tm1);
        u64 v   = f2mul(C075p, u);
        u64 W3  = f2mul(v, ctp);
        u64 W0  = f2sub(v, W3);
        u64 omt = f2sub(ONEp, ctp);
        u64 z   = f2mul(u, ctp);
        u64 h   = f2sub(omt, u);
        u64 W1  = f2fma(C125p, z, h);
        u64 r_  = f2sub(ONEp, W0);
        r_      = f2sub(r_, W1);
        u64 W2  = f2sub(r_, W3);

        float w0A,w0B,w1A,w1B,w2A,w2B,w3A,w3B;
        upk(w0A, w0B, W0); upk(w1A, w1B, W1);
        upk(w2A, w2B, W2); upk(w3A, w3B, W3);

        float accA0 = fmaf(a0x, w0A, fmaf(a1x, w1A, fmaf(a2x, w2A, a3x * w3A)));
        float accA1 = fmaf(a0y, w0A, fmaf(a1y, w1A, fmaf(a2y, w2A, a3y * w3A)));
        float accB0 = fmaf(b0x, w0B, fmaf(b1x, w1B, fmaf(b2x, w2B, b3x * w3B)));
        float accB1 = fmaf(b0y, w0B, fmaf(b1y, w1B, fmaf(b2y, w2B, b3y * w3B)));

        const int iA = 2 * p - n;             // out float2 index = s*16 + n
        out[iA]        = make_float2(accA0, accA1);
        out[iA + NLVL] = make_float2(accB0, accB1);

        // ---- rotate pipeline ----
        ctp = ntp; cadA = nadA; cadB = nadB;
        q0 = f0; q1 = f1; q2 = f2v;
    }
}

extern "C" void kernel_launch(void* const* d_in, const int* in_sizes, int n_in,
                              void* d_out, int out_size)
{
    const float* x     = (const float*)d_in[0];
    const float* grids = (const float*)d_in[1];
    const float* G     = (const float*)d_in[2];
    const float* H     = (const float*)d_in[3];
    (void)n_in; (void)out_size;

    const int B       = in_sizes[0] / 3;
    const int n_pairs = (B / 2) * NLVL;

    const int smem_bytes = PADW * NLVL * (int)sizeof(float2);   // 128512

    cudaFuncSetAttribute(trig_hash_kernel,
                         cudaFuncAttributeMaxDynamicSharedMemorySize, smem_bytes);

    int sm_count = 148;
    cudaDeviceGetAttribute(&sm_count, cudaDevAttrMultiProcessorCount, 0);

    trig_hash_kernel<<<sm_count, TPB, smem_bytes>>>(
        x, grids, G, H, (float2*)d_out, n_pairs);
}

// round 13
// speedup vs baseline: 1.0694x; 1.0694x over previous
#include <cuda_runtime.h>

#define NLVL   16
#define WIDTH  1000
#define PADW   (WIDTH + 4)     // w in [-2, 1001]
#define TPB    1024            // 32 warps; pipelined loop fits 64 regs (R12 evidence)

typedef unsigned long long u64;
typedef unsigned int       u32;

// ---------------- packed f32x2 helpers ----------------
__device__ __forceinline__ u64 pk(float lo, float hi) {
    u64 r; asm("mov.b64 %0, {%1,%2};" : "=l"(r) : "f"(lo), "f"(hi)); return r;
}
__device__ __forceinline__ void upk(float& lo, float& hi, u64 v) {
    asm("mov.b64 {%0,%1}, %2;" : "=f"(lo), "=f"(hi) : "l"(v));
}
__device__ __forceinline__ u64 f2fma(u64 a, u64 b, u64 c) {
    u64 r; asm("fma.rn.f32x2 %0, %1, %2, %3;" : "=l"(r) : "l"(a), "l"(b), "l"(c)); return r;
}
__device__ __forceinline__ u64 f2add(u64 a, u64 b) {
    u64 r; asm("add.rn.f32x2 %0, %1, %2;" : "=l"(r) : "l"(a), "l"(b)); return r;
}
__device__ __forceinline__ u64 f2sub(u64 a, u64 b) {
    u64 r; asm("sub.rn.f32x2 %0, %1, %2;" : "=l"(r) : "l"(a), "l"(b)); return r;
}
__device__ __forceinline__ u64 f2mul(u64 a, u64 b) {
    u64 r; asm("mul.rn.f32x2 %0, %1, %2;" : "=l"(r) : "l"(a), "l"(b)); return r;
}
__device__ __forceinline__ u64 bc(float v) { return pk(v, v); }

__device__ __forceinline__ float hwsin(float r) {   // r in [-pi, pi]
    float s; asm("sin.approx.f32 %0, %1;" : "=f"(s) : "f"(r)); return s;
}

__device__ __forceinline__ u64 lds64(u32 addr, int imm_off) {
    u64 v;
    asm("ld.shared.b64 %0, [%1];" : "=l"(v) : "r"(addr + (u32)imm_off));
    return v;
}

__global__ __launch_bounds__(TPB, 1)
void trig_hash_kernel(const float* __restrict__ x,
                      const float* __restrict__ grids,
                      const float* __restrict__ G,
                      const float* __restrict__ H,
                      float2* __restrict__ out,
                      int n_pairs)     // (B/2)*16
{
    extern __shared__ float2 gsm[];    // [(w+2)*16 + n] : conflict-free (half-warp phases)

    // Stage grids (N,C,W) -> transposed padded smem. Zeros outside [0,W).
    for (int j = threadIdx.x; j < PADW * NLVL; j += TPB) {
        int n = j & (NLVL - 1);
        int w = (j >> 4) - 2;
        float c0 = 0.f, c1 = 0.f;
        if ((unsigned)w < (unsigned)WIDTH) {
            c0 = grids[(n * 2 + 0) * WIDTH + w];
            c1 = grids[(n * 2 + 1) * WIDTH + w];
        }
        gsm[j] = make_float2(c0, c1);
    }
    __syncthreads();

    const int gtid   = blockIdx.x * TPB + threadIdx.x;
    const int stride = gridDim.x * TPB;       // multiple of 16
    const int n      = gtid & (NLVL - 1);

    // Per-level constants pre-scaled to TURNS (fold 1/2pi into G, H).
    const float S = 0.15915494309189535f;
    const u64 G00 = bc(G[  0 + n]*S), G01 = bc(G[ 16 + n]*S), G02 = bc(G[ 32 + n]*S);
    const u64 G10 = bc(G[ 48 + n]*S), G11 = bc(G[ 64 + n]*S), G12 = bc(G[ 80 + n]*S);
    const u64 G20 = bc(G[ 96 + n]*S), G21 = bc(G[112 + n]*S), G22 = bc(G[128 + n]*S);
    const u64 H0  = bc(H[  0 + n]*S), H1  = bc(H[ 16 + n]*S), H2  = bc(H[ 32 + n]*S);

    const u64 MAGIC = bc(12582912.0f);               // 1.5 * 2^23
    const u64 TWOPI = bc(6.2831853071795865f);
    const u64 ONEp  = bc(1.0f);
    const u64 C075p = bc(0.75f);
    const u64 C125p = bc(1.25f);
    const float MAG499 = 12583411.0f;                // 12582912 + 499, exact

    u32 smbase;
    asm("{ .reg .u64 t; cvta.to.shared.u64 t, %1; cvt.u32.u64 %0, t; }"
        : "=r"(smbase) : "l"(gsm));
    // addr(tap0) = bits(bb)*128 + addrc   (0x4B400000*128 mod 2^32 = 0xA0000000)
    const u32 addrc = smbase + 128u + (u32)(n * 8) - 0xA0000000u;

    // ================= stage-1: x -> (t packed, tap addresses) =================
    auto stage1 = [&](float2 s0, float2 s1, float2 s2,
                      u64& tp_o, u32& adA_o, u32& adB_o) {
        u64 X0 = pk(s0.x, s1.y);
        u64 X1 = pk(s0.y, s2.x);
        u64 X2 = pk(s1.x, s2.y);
        u64 a0 = f2fma(X0, G00, f2fma(X1, G10, f2fma(X2, G20, H0)));
        u64 a1 = f2fma(X0, G01, f2fma(X1, G11, f2fma(X2, G21, H1)));
        u64 a2 = f2fma(X0, G02, f2fma(X1, G12, f2fma(X2, G22, H2)));
        // turns-domain reduction: rt = a - rint(a) (exact), then *2pi
        u64 kb0 = f2add(a0, MAGIC), kb1 = f2add(a1, MAGIC), kb2 = f2add(a2, MAGIC);
        u64 rr0 = f2mul(f2sub(a0, f2sub(kb0, MAGIC)), TWOPI);
        u64 rr1 = f2mul(f2sub(a1, f2sub(kb1, MAGIC)), TWOPI);
        u64 rr2 = f2mul(f2sub(a2, f2sub(kb2, MAGIC)), TWOPI);
        float r0A, r0B, r1A, r1B, r2A, r2B;
        upk(r0A, r0B, rr0); upk(r1A, r1B, rr1); upk(r2A, r2B, rr2);
        float gxA = hwsin(r0A) * hwsin(r1A) * hwsin(r2A);
        float gxB = hwsin(r0B) * hwsin(r1B) * hwsin(r2B);
        // fused ix chain: ix = 500*gx + 499.5
        float bbA = fmaf(gxA, 500.0f, MAG499);        // MAGIC + floor(ix)
        float bbB = fmaf(gxB, 500.0f, MAG499);
        float xfA = bbA - 12582912.0f;
        float xfB = bbB - 12582912.0f;
        float tA  = fmaf(gxA, 500.0f, 499.5f - xfA);  // t = ix - base
        float tB  = fmaf(gxB, 500.0f, 499.5f - xfB);
        tp_o  = pk(tA, tB);
        adA_o = __float_as_uint(bbA) * 128u + addrc;
        adB_o = __float_as_uint(bbB) * 128u + addrc;
    };

    // ================= prologue =================
    u64 ctp; u32 cadA, cadB;
    {
        int g = ((gtid < n_pairs) ? gtid : 0) >> 4;
        const float2* xp = (const float2*)(x + 6 * g);
        stage1(xp[0], xp[1], xp[2], ctp, cadA, cadB);
    }
    float2 q0, q1, q2;
    {
        int pq = gtid + stride;
        int g  = ((pq < n_pairs) ? pq : ((gtid < n_pairs) ? gtid : 0)) >> 4;
        const float2* xp = (const float2*)(x + 6 * g);
        q0 = xp[0]; q1 = xp[1]; q2 = xp[2];
    }

    for (int p = gtid; p < n_pairs; p += stride) {
        // ---- 8 channel-packed tap loads for CURRENT p (carried addresses) ----
        u64 vA0 = lds64(cadA,   0), vA1 = lds64(cadA, 128);
        u64 vA2 = lds64(cadA, 256), vA3 = lds64(cadA, 384);
        u64 vB0 = lds64(cadB,   0), vB1 = lds64(cadB, 128);
        u64 vB2 = lds64(cadB, 256), vB3 = lds64(cadB, 384);

        // ---- prefetch x two iterations ahead ----
        int pf = p + 2 * stride;
        int gf = ((pf < n_pairs) ? pf : p) >> 4;
        const float2* xf = (const float2*)(x + 6 * gf);
        float2 f0 = xf[0], f1 = xf[1], f2v = xf[2];

        // ---- stage-1 for p+stride (long independent stream: hides LDS+MUFU) ----
        u64 ntp; u32 nadA, nadB;
        stage1(q0, q1, q2, ntp, nadA, nadB);

        // ---- weights for CURRENT p from carried t (u = t^2 - t factorization) ----
        u64 tm1 = f2sub(ctp, ONEp);
        u64 u   = f2mul(ctp, tm1);
        u64 v   = f2mul(C075p, u);
        u64 W3  = f2mul(v, ctp);
        u64 W0  = f2sub(v, W3);
        u64 omt = f2sub(ONEp, ctp);
        u64 z   = f2mul(u, ctp);
        u64 h   = f2sub(omt, u);
        u64 W1  = f2fma(C125p, z, h);
        u64 r_  = f2sub(ONEp, W0);
        r_      = f2sub(r_, W1);
        u64 W2  = f2sub(r_, W3);

        float w0A,w0B,w1A,w1B,w2A,w2B,w3A,w3B;
        upk(w0A, w0B, W0); upk(w1A, w1B, W1);
        upk(w2A, w2B, W2); upk(w3A, w3B, W3);

        // ---- channel-packed accumulation: acc(c0,c1) += tap(c0,c1) * (w,w) ----
        u64 accA = f2mul(vA3, pk(w3A, w3A));
        accA = f2fma(vA2, pk(w2A, w2A), accA);
        accA = f2fma(vA1, pk(w1A, w1A), accA);
        accA = f2fma(vA0, pk(w0A, w0A), accA);
        u64 accB = f2mul(vB3, pk(w3B, w3B));
        accB = f2fma(vB2, pk(w2B, w2B), accB);
        accB = f2fma(vB1, pk(w1B, w1B), accB);
        accB = f2fma(vB0, pk(w0B, w0B), accB);

        const int iA = 2 * p - n;             // out float2 index = s*16 + n
        ((u64*)out)[iA]        = accA;
        ((u64*)out)[iA + NLVL] = accB;

        // ---- rotate pipeline ----
        ctp = ntp; cadA = nadA; cadB = nadB;
        q0 = f0; q1 = f1; q2 = f2v;
    }
}

extern "C" void kernel_launch(void* const* d_in, const int* in_sizes, int n_in,
                              void* d_out, int out_size)
{
    const float* x     = (const float*)d_in[0];
    const float* grids = (const float*)d_in[1];
    const float* G     = (const float*)d_in[2];
    const float* H     = (const float*)d_in[3];
    (void)n_in; (void)out_size;

    const int B       = in_sizes[0] / 3;
    const int n_pairs = (B / 2) * NLVL;

    const int smem_bytes = PADW * NLVL * (int)sizeof(float2);   // 128512

    cudaFuncSetAttribute(trig_hash_kernel,
                         cudaFuncAttributeMaxDynamicSharedMemorySize, smem_bytes);

    int sm_count = 148;
    cudaDeviceGetAttribute(&sm_count, cudaDevAttrMultiProcessorCount, 0);

    trig_hash_kernel<<<sm_count, TPB, smem_bytes>>>(
        x, grids, G, H, (float2*)d_out, n_pairs);
}

// round 14
// speedup vs baseline: 1.1007x; 1.0292x over previous
#include <cuda_runtime.h>

#define NLVL   16
#define WIDTH  1000
#define PADW   (WIDTH + 4)     // w in [-2, 1001]
#define TPB    1024

typedef unsigned long long u64;
typedef unsigned int       u32;

// ---------------- packed f32x2 helpers ----------------
__device__ __forceinline__ u64 pk(float lo, float hi) {
    u64 r; asm("mov.b64 %0, {%1,%2};" : "=l"(r) : "f"(lo), "f"(hi)); return r;
}
__device__ __forceinline__ void upk(float& lo, float& hi, u64 v) {
    asm("mov.b64 {%0,%1}, %2;" : "=f"(lo), "=f"(hi) : "l"(v));
}
__device__ __forceinline__ u64 f2fma(u64 a, u64 b, u64 c) {
    u64 r; asm("fma.rn.f32x2 %0, %1, %2, %3;" : "=l"(r) : "l"(a), "l"(b), "l"(c)); return r;
}
__device__ __forceinline__ u64 f2add(u64 a, u64 b) {
    u64 r; asm("add.rn.f32x2 %0, %1, %2;" : "=l"(r) : "l"(a), "l"(b)); return r;
}
__device__ __forceinline__ u64 f2sub(u64 a, u64 b) {
    u64 r; asm("sub.rn.f32x2 %0, %1, %2;" : "=l"(r) : "l"(a), "l"(b)); return r;
}
__device__ __forceinline__ u64 f2mul(u64 a, u64 b) {
    u64 r; asm("mul.rn.f32x2 %0, %1, %2;" : "=l"(r) : "l"(a), "l"(b)); return r;
}

__device__ __forceinline__ float hwsin(float r) {   // r in [-pi, pi]
    float s; asm("sin.approx.f32 %0, %1;" : "=f"(s) : "f"(r)); return s;
}

__device__ __forceinline__ u64 lds64(u32 addr, int imm_off) {
    u64 v;
    asm("ld.shared.b64 %0, [%1];" : "=l"(v) : "r"(addr + (u32)imm_off));
    return v;
}

__global__ __launch_bounds__(TPB, 1)
void trig_hash_kernel(const float* __restrict__ x,
                      const float* __restrict__ grids,
                      const float* __restrict__ G,
                      const float* __restrict__ H,
                      float2* __restrict__ out,
                      int n_duos)      // B*8 : thread-iteration = (sample, level-duo)
{
    extern __shared__ float2 gsm[];    // [(w+2)*16 + n] : conflict-free (half-warp phases)

    // Stage grids (N,C,W) -> transposed padded smem. Zeros outside [0,W).
    for (int j = threadIdx.x; j < PADW * NLVL; j += TPB) {
        int n = j & (NLVL - 1);
        int w = (j >> 4) - 2;
        float c0 = 0.f, c1 = 0.f;
        if ((unsigned)w < (unsigned)WIDTH) {
            c0 = grids[(n * 2 + 0) * WIDTH + w];
            c1 = grids[(n * 2 + 1) * WIDTH + w];
        }
        gsm[j] = make_float2(c0, c1);
    }
    __syncthreads();

    const int gtid   = blockIdx.x * TPB + threadIdx.x;
    const int stride = gridDim.x * TPB;       // multiple of 8
    const int m      = gtid & 7;              // level duo: levels 2m, 2m+1

    // Per-duo constants, TURNS-scaled, packed (level 2m in lo, 2m+1 in hi).
    const float S = 0.15915494309189535f;
    const int n0 = 2 * m, n1 = 2 * m + 1;
    const u64 G00 = pk(G[  0+n0]*S, G[  0+n1]*S), G01 = pk(G[ 16+n0]*S, G[ 16+n1]*S),
              G02 = pk(G[ 32+n0]*S, G[ 32+n1]*S);
    const u64 G10 = pk(G[ 48+n0]*S, G[ 48+n1]*S), G11 = pk(G[ 64+n0]*S, G[ 64+n1]*S),
              G12 = pk(G[ 80+n0]*S, G[ 80+n1]*S);
    const u64 G20 = pk(G[ 96+n0]*S, G[ 96+n1]*S), G21 = pk(G[112+n0]*S, G[112+n1]*S),
              G22 = pk(G[128+n0]*S, G[128+n1]*S);
    const u64 H0  = pk(H[  0+n0]*S, H[  0+n1]*S), H1  = pk(H[ 16+n0]*S, H[ 16+n1]*S),
              H2  = pk(H[ 32+n0]*S, H[ 32+n1]*S);

    const u64 MAGIC = pk(12582912.0f, 12582912.0f);      // 1.5 * 2^23
    const u64 TWOPI = pk(6.2831853071795865f, 6.2831853071795865f);
    const u64 ONEp  = pk(1.0f, 1.0f);
    const u64 C075p = pk(0.75f, 0.75f);
    const u64 C125p = pk(1.25f, 1.25f);
    const float MAG499 = 12583411.0f;                    // 12582912 + 499, exact

    u32 smbase;
    asm("{ .reg .u64 t; cvta.to.shared.u64 t, %1; cvt.u32.u64 %0, t; }"
        : "=r"(smbase) : "l"(gsm));
    // item0 (level 2m) tap0 addr = bits(bb)*128 + addrc ; item1 = +8 bytes
    const u32 addrc = smbase + 128u + (u32)(16 * m) - 0xA0000000u;

    // ---- preload x for the first iteration (one sample = 3 scalars) ----
    float q0, q1, q2;
    {
        const float* xp = x + 3 * (((gtid < n_duos) ? gtid : 0) >> 3);
        q0 = xp[0]; q1 = xp[1]; q2 = xp[2];
    }

    for (int p = gtid; p < n_duos; p += stride) {
        // ---- prefetch next iteration's x ----
        int pn = p + stride;
        const float* xn = x + 3 * ((((pn < n_duos) ? pn : p)) >> 3);
        float f0 = xn[0], f1 = xn[1], f2v = xn[2];

        // ---- broadcast-sample packed a-chain (turns) : lo=level 2m, hi=2m+1 ----
        u64 X0 = pk(q0, q0);
        u64 X1 = pk(q1, q1);
        u64 X2 = pk(q2, q2);
        u64 a0 = f2fma(X0, G00, f2fma(X1, G10, f2fma(X2, G20, H0)));
        u64 a1 = f2fma(X0, G01, f2fma(X1, G11, f2fma(X2, G21, H1)));
        u64 a2 = f2fma(X0, G02, f2fma(X1, G12, f2fma(X2, G22, H2)));

        // turns reduction: rt = a - rint(a) (exact), then *2pi
        u64 kb0 = f2add(a0, MAGIC), kb1 = f2add(a1, MAGIC), kb2 = f2add(a2, MAGIC);
        u64 rr0 = f2mul(f2sub(a0, f2sub(kb0, MAGIC)), TWOPI);
        u64 rr1 = f2mul(f2sub(a1, f2sub(kb1, MAGIC)), TWOPI);
        u64 rr2 = f2mul(f2sub(a2, f2sub(kb2, MAGIC)), TWOPI);
        float r0A, r0B, r1A, r1B, r2A, r2B;
        upk(r0A, r0B, rr0); upk(r1A, r1B, rr1); upk(r2A, r2B, rr2);

        float gxA = hwsin(r0A) * hwsin(r1A) * hwsin(r2A);   // level 2m
        float gxB = hwsin(r0B) * hwsin(r1B) * hwsin(r2B);   // level 2m+1

        // fused ix chain: ix = 500*gx + 499.5
        float bbA = fmaf(gxA, 500.0f, MAG499);        // MAGIC + floor(ix)
        float bbB = fmaf(gxB, 500.0f, MAG499);
        float xfA = bbA - 12582912.0f;
        float xfB = bbB - 12582912.0f;
        float tA  = fmaf(gxA, 500.0f, 499.5f - xfA);  // t = ix - base
        float tB  = fmaf(gxB, 500.0f, 499.5f - xfB);

        // ---- 8 channel-packed tap loads ----
        const u32 adA = __float_as_uint(bbA) * 128u + addrc;        // level 2m
        const u32 adB = __float_as_uint(bbB) * 128u + addrc + 8u;   // level 2m+1
        u64 vA0 = lds64(adA,   0), vA1 = lds64(adA, 128);
        u64 vA2 = lds64(adA, 256), vA3 = lds64(adA, 384);
        u64 vB0 = lds64(adB,   0), vB1 = lds64(adB, 128);
        u64 vB2 = lds64(adB, 256), vB3 = lds64(adB, 384);

        // ---- packed cubic weights (A in lo, B in hi), u = t^2 - t ----
        u64 tp  = pk(tA, tB);
        u64 tm1 = f2sub(tp, ONEp);
        u64 u   = f2mul(tp, tm1);
        u64 v   = f2mul(C075p, u);
        u64 W3  = f2mul(v, tp);
        u64 W0  = f2sub(v, W3);
        u64 omt = f2sub(ONEp, tp);
        u64 z   = f2mul(u, tp);
        u64 h   = f2sub(omt, u);
        u64 W1  = f2fma(C125p, z, h);
        u64 r_  = f2sub(ONEp, W0);
        r_      = f2sub(r_, W1);
        u64 W2  = f2sub(r_, W3);

        float w0A,w0B,w1A,w1B,w2A,w2B,w3A,w3B;
        upk(w0A, w0B, W0); upk(w1A, w1B, W1);
        upk(w2A, w2B, W2); upk(w3A, w3B, W3);

        // ---- channel-packed accumulation ----
        u64 accA = f2mul(vA3, pk(w3A, w3A));
        accA = f2fma(vA2, pk(w2A, w2A), accA);
        accA = f2fma(vA1, pk(w1A, w1A), accA);
        accA = f2fma(vA0, pk(w0A, w0A), accA);
        u64 accB = f2mul(vB3, pk(w3B, w3B));
        accB = f2fma(vB2, pk(w2B, w2B), accB);
        accB = f2fma(vB1, pk(w1B, w1B), accB);
        accB = f2fma(vB0, pk(w0B, w0B), accB);

        // outputs adjacent: float2 idx s*16+2m = 2p and 2p+1 -> one STG.128
        ulonglong2 o; o.x = accA; o.y = accB;
        ((ulonglong2*)out)[p] = o;

        // rotate x
        q0 = f0; q1 = f1; q2 = f2v;
    }
}

extern "C" void kernel_launch(void* const* d_in, const int* in_sizes, int n_in,
                              void* d_out, int out_size)
{
    const float* x     = (const float*)d_in[0];
    const float* grids = (const float*)d_in[1];
    const float* G     = (const float*)d_in[2];
    const float* H     = (const float*)d_in[3];
    (void)n_in; (void)out_size;

    const int B      = in_sizes[0] / 3;
    const int n_duos = B * 8;            // (sample, level-duo) work items

    const int smem_bytes = PADW * NLVL * (int)sizeof(float2);   // 128512

    cudaFuncSetAttribute(trig_hash_kernel,
                         cudaFuncAttributeMaxDynamicSharedMemorySize, smem_bytes);

    int sm_count = 148;
    cudaDeviceGetAttribute(&sm_count, cudaDevAttrMultiProcessorCount, 0);

    trig_hash_kernel<<<sm_count, TPB, smem_bytes>>>(
        x, grids, G, H, (float2*)d_out, n_duos);
}